// round 5
// baseline (speedup 1.0000x reference)
#include <cuda_runtime.h>
#include <cuda_bf16.h>
#include <math.h>

#define T_LEN    8192
#define VOCAB    50257
#define NCHUNK   74               // 8 qblocks x 74 chunks = 592 CTAs = exactly 4/SM
#define NQBLK    8
#define QBLK     1024             // queries per CTA
#define NTHREADS 256
#define QPT      4
#define KMAX     111              // ceil(8192/74)

// scratch (device globals; no allocation allowed)
__device__ float4 g_qp[T_LEN];                // q' = QSCALE * (Wk^T Wq) p
__device__ float4 g_p[T_LEN];                 // p with w=1.0f
__device__ float4 g_part[NCHUNK * T_LEN];     // per-chunk partial (sum e*p, sum e)

__device__ __forceinline__ float ex2f(float x) {
    float r; asm("ex2.approx.f32 %0, %1;" : "=f"(r) : "f"(x)); return r;
}

// ---------------------------------------------------------------------------
// Kernel 1: gather + posenc; emit p and q' = QSCALE*(Wk^T Wq) p.
// k, v never materialized: s_ij = q'_i . p_j ; out = Wv (sum e p)/sum e.
// ---------------------------------------------------------------------------
__global__ __launch_bounds__(256)
void prep_kernel(const int* __restrict__ x,
                 const float* __restrict__ emb,
                 const float* __restrict__ Wk,
                 const float* __restrict__ Wq) {
    int t = blockIdx.x * blockDim.x + threadIdx.x;
    if (t >= T_LEN) return;

    int xi = x[t];
    xi = min(max(xi, 0), VOCAB - 1);

    // positional encoding — mirror reference fp32 op order
    float a  = 6.28f * (float)t;
    float p0 = emb[xi * 3 + 0] + cosf(a / 25.0f);
    float p1 = emb[xi * 3 + 1] + sinf(a / 25.0f);
    float p2 = emb[xi * 3 + 2] + sinf(a / 5.0f);

    const float QSCALE = 0.8329465708f;  // log2(e) / sqrt(3)

    // M = Wk^T Wq applied to p
    float q0 = 0.f, q1 = 0.f, q2 = 0.f;
    #pragma unroll
    for (int aa = 0; aa < 3; ++aa) {
        float qq = fmaf(Wq[aa * 3 + 0], p0,
                   fmaf(Wq[aa * 3 + 1], p1, Wq[aa * 3 + 2] * p2)); // (Wq p)_a
        q0 = fmaf(Wk[aa * 3 + 0], qq, q0);
        q1 = fmaf(Wk[aa * 3 + 1], qq, q1);
        q2 = fmaf(Wk[aa * 3 + 2], qq, q2);
    }
    g_qp[t] = make_float4(q0 * QSCALE, q1 * QSCALE, q2 * QSCALE, 0.0f);
    g_p[t]  = make_float4(p0, p1, p2, 1.0f);
}

// ---------------------------------------------------------------------------
// Kernel 2: fused attention, no-max softmax (scores bounded << 88).
// grid = (8, 74) = 592 CTAs x 256 thr = 4 CTAs/SM, 8 warps/SMSP, one wave.
// Inner loop: 1 LDS.128 + per query {3 FMA dot, ex2, 4 FMA-class acc}.
// ---------------------------------------------------------------------------
__global__ __launch_bounds__(NTHREADS)
void attn_kernel() {
    __shared__ float4 sp[KMAX];

    const int tid  = threadIdx.x;
    const int c    = blockIdx.y;
    const int kbeg = (c * T_LEN) / NCHUNK;
    const int kend = ((c + 1) * T_LEN) / NCHUNK;
    const int klen = kend - kbeg;

    for (int i = tid; i < klen; i += NTHREADS)
        sp[i] = g_p[kbeg + i];
    __syncthreads();

    const int qbase = blockIdx.x * QBLK + tid;
    float3 q[QPT];
    #pragma unroll
    for (int u = 0; u < QPT; ++u) {
        float4 t4 = g_qp[qbase + u * NTHREADS];
        q[u] = make_float3(t4.x, t4.y, t4.z);
    }

    float den[QPT], a0[QPT], a1[QPT], a2[QPT];
    #pragma unroll
    for (int u = 0; u < QPT; ++u) { den[u] = a0[u] = a1[u] = a2[u] = 0.0f; }

    #pragma unroll 3
    for (int j = 0; j < klen; ++j) {
        float4 p = sp[j];
        #pragma unroll
        for (int u = 0; u < QPT; ++u) {
            float s = fmaf(q[u].x, p.x, fmaf(q[u].y, p.y, q[u].z * p.z));
            float e = ex2f(s);
            den[u] += e;
            a0[u] = fmaf(e, p.x, a0[u]);
            a1[u] = fmaf(e, p.y, a1[u]);
            a2[u] = fmaf(e, p.z, a2[u]);
        }
    }

    #pragma unroll
    for (int u = 0; u < QPT; ++u)
        g_part[c * T_LEN + qbase + u * NTHREADS] =
            make_float4(a0[u], a1[u], a2[u], den[u]);
}

// ---------------------------------------------------------------------------
// Kernel 3: deterministic fixed-order reduce over NCHUNK partials, then
// apply Wv once per query and divide.
// ---------------------------------------------------------------------------
__global__ __launch_bounds__(256)
void reduce_kernel(const float* __restrict__ Wv, float* __restrict__ out) {
    int t = blockIdx.x * blockDim.x + threadIdx.x;
    if (t >= T_LEN) return;

    float r0 = 0.f, r1 = 0.f, r2 = 0.f, rd = 0.f;
    #pragma unroll 2
    for (int s = 0; s < NCHUNK; ++s) {
        float4 p = g_part[s * T_LEN + t];
        r0 += p.x; r1 += p.y; r2 += p.z; rd += p.w;
    }
    float inv = 1.0f / rd;
    out[t * 3 + 0] = fmaf(Wv[0], r0, fmaf(Wv[1], r1, Wv[2] * r2)) * inv;
    out[t * 3 + 1] = fmaf(Wv[3], r0, fmaf(Wv[4], r1, Wv[5] * r2)) * inv;
    out[t * 3 + 2] = fmaf(Wv[6], r0, fmaf(Wv[7], r1, Wv[8] * r2)) * inv;
}

extern "C" void kernel_launch(void* const* d_in, const int* in_sizes, int n_in,
                              void* d_out, int out_size) {
    const int*   x   = (const int*)  d_in[0];
    const float* emb = (const float*)d_in[1];
    const float* Wk  = (const float*)d_in[2];
    const float* Wq  = (const float*)d_in[3];
    const float* Wv  = (const float*)d_in[4];
    float* out = (float*)d_out;

    prep_kernel<<<T_LEN / 256, 256>>>(x, emb, Wk, Wq);
    attn_kernel<<<dim3(NQBLK, NCHUNK), NTHREADS>>>();
    reduce_kernel<<<T_LEN / 256, 256>>>(Wv, out);
}

// round 6
// speedup vs baseline: 1.1761x; 1.1761x over previous
#include <cuda_runtime.h>
#include <cuda_bf16.h>
#include <math.h>

#define T_LEN    8192
#define VOCAB    50257
#define NCHUNK   37               // 16 qblocks x 37 chunks = 592 CTAs = exactly 4/SM
#define NQBLK    16
#define QBLK     512              // queries per CTA
#define NTHREADS 128
#define QPT      4
#define KMAX     222              // fixed chunk width; 37*222 = 8214 (last chunk padded)

// scratch (device globals; no allocation allowed)
__device__ float4 g_qp[T_LEN];                // q' = QSCALE * (Wk^T Wq) p
__device__ float4 g_p[T_LEN];                 // p with w=1.0f
__device__ float4 g_part[NCHUNK * T_LEN];     // per-chunk partial (sum e*p, sum e)

__device__ __forceinline__ float ex2f(float x) {
    float r; asm("ex2.approx.f32 %0, %1;" : "=f"(r) : "f"(x)); return r;
}

// ---------------------------------------------------------------------------
// Kernel 1: gather + posenc; emit p and q' = QSCALE*(Wk^T Wq) p.
// k, v never materialized: s_ij = q'_i . p_j ; out = Wv (sum e p)/sum e.
// ---------------------------------------------------------------------------
__global__ __launch_bounds__(256)
void prep_kernel(const int* __restrict__ x,
                 const float* __restrict__ emb,
                 const float* __restrict__ Wk,
                 const float* __restrict__ Wq) {
    int t = blockIdx.x * blockDim.x + threadIdx.x;
    if (t >= T_LEN) return;

    int xi = x[t];
    xi = min(max(xi, 0), VOCAB - 1);

    // positional encoding — mirror reference fp32 op order
    float a  = 6.28f * (float)t;
    float p0 = emb[xi * 3 + 0] + cosf(a / 25.0f);
    float p1 = emb[xi * 3 + 1] + sinf(a / 25.0f);
    float p2 = emb[xi * 3 + 2] + sinf(a / 5.0f);

    const float QSCALE = 0.8329465708f;  // log2(e) / sqrt(3)

    // q' = QSCALE * (Wk^T Wq) p
    float q0 = 0.f, q1 = 0.f, q2 = 0.f;
    #pragma unroll
    for (int aa = 0; aa < 3; ++aa) {
        float qq = fmaf(Wq[aa * 3 + 0], p0,
                   fmaf(Wq[aa * 3 + 1], p1, Wq[aa * 3 + 2] * p2)); // (Wq p)_a
        q0 = fmaf(Wk[aa * 3 + 0], qq, q0);
        q1 = fmaf(Wk[aa * 3 + 1], qq, q1);
        q2 = fmaf(Wk[aa * 3 + 2], qq, q2);
    }
    g_qp[t] = make_float4(q0 * QSCALE, q1 * QSCALE, q2 * QSCALE, 0.0f);
    g_p[t]  = make_float4(p0, p1, p2, 1.0f);
}

// ---------------------------------------------------------------------------
// Kernel 2: fused attention, no-max softmax (scores bounded << 88).
// grid = (16, 37) = 592 CTAs x 128 thr = exactly 4 CTAs/SM, 4 warps/SMSP.
// COMPILE-TIME trip count KMAX=222; last chunk zero-padded in smem, and the
// pad is exactly neutral because den accumulates e*p.w (pad p == 0).
// ---------------------------------------------------------------------------
__global__ __launch_bounds__(NTHREADS)
void attn_kernel() {
    __shared__ float4 sp[KMAX];

    const int tid  = threadIdx.x;
    const int kbeg = blockIdx.y * KMAX;

    #pragma unroll
    for (int i = tid; i < KMAX; i += NTHREADS) {
        int idx = kbeg + i;
        sp[i] = (idx < T_LEN) ? g_p[idx] : make_float4(0.f, 0.f, 0.f, 0.f);
    }
    __syncthreads();

    const int qbase = blockIdx.x * QBLK + tid;
    float3 q[QPT];
    #pragma unroll
    for (int u = 0; u < QPT; ++u) {
        float4 t4 = g_qp[qbase + u * NTHREADS];
        q[u] = make_float3(t4.x, t4.y, t4.z);
    }

    float den[QPT], a0[QPT], a1[QPT], a2[QPT];
    #pragma unroll
    for (int u = 0; u < QPT; ++u) { den[u] = a0[u] = a1[u] = a2[u] = 0.0f; }

    #pragma unroll 2
    for (int j = 0; j < KMAX; ++j) {
        float4 p = sp[j];
        #pragma unroll
        for (int u = 0; u < QPT; ++u) {
            float s = fmaf(q[u].x, p.x, fmaf(q[u].y, p.y, q[u].z * p.z));
            float e = ex2f(s);
            den[u] = fmaf(e, p.w, den[u]);   // p.w = 1 real key, 0 pad
            a0[u]  = fmaf(e, p.x, a0[u]);
            a1[u]  = fmaf(e, p.y, a1[u]);
            a2[u]  = fmaf(e, p.z, a2[u]);
        }
    }

    #pragma unroll
    for (int u = 0; u < QPT; ++u)
        g_part[blockIdx.y * T_LEN + qbase + u * NTHREADS] =
            make_float4(a0[u], a1[u], a2[u], den[u]);
}

// ---------------------------------------------------------------------------
// Kernel 3: deterministic fixed-order reduce over NCHUNK partials, then
// apply Wv once per query and divide.
// ---------------------------------------------------------------------------
__global__ __launch_bounds__(256)
void reduce_kernel(const float* __restrict__ Wv, float* __restrict__ out) {
    int t = blockIdx.x * blockDim.x + threadIdx.x;
    if (t >= T_LEN) return;

    float r0 = 0.f, r1 = 0.f, r2 = 0.f, rd = 0.f;
    #pragma unroll
    for (int s = 0; s < NCHUNK; ++s) {
        float4 p = g_part[s * T_LEN + t];
        r0 += p.x; r1 += p.y; r2 += p.z; rd += p.w;
    }
    float inv = 1.0f / rd;
    out[t * 3 + 0] = fmaf(Wv[0], r0, fmaf(Wv[1], r1, Wv[2] * r2)) * inv;
    out[t * 3 + 1] = fmaf(Wv[3], r0, fmaf(Wv[4], r1, Wv[5] * r2)) * inv;
    out[t * 3 + 2] = fmaf(Wv[6], r0, fmaf(Wv[7], r1, Wv[8] * r2)) * inv;
}

extern "C" void kernel_launch(void* const* d_in, const int* in_sizes, int n_in,
                              void* d_out, int out_size) {
    const int*   x   = (const int*)  d_in[0];
    const float* emb = (const float*)d_in[1];
    const float* Wk  = (const float*)d_in[2];
    const float* Wq  = (const float*)d_in[3];
    const float* Wv  = (const float*)d_in[4];
    float* out = (float*)d_out;

    prep_kernel<<<T_LEN / 256, 256>>>(x, emb, Wk, Wq);
    attn_kernel<<<dim3(NQBLK, NCHUNK), NTHREADS>>>();
    reduce_kernel<<<T_LEN / 256, 256>>>(Wv, out);
}